// round 5
// baseline (speedup 1.0000x reference)
#include <cuda_runtime.h>
#include <cuda_bf16.h>

// preds:   (16, 19, 512, 512) float32  = 79,691,776 elems
// targets: (16, 1024, 1024)   labels in [0,19) (delivered as int32)
// grid 16 -> 32x32 cells/batch, 16x16 px each.
//
// Single fused kernel:
//   blocks [0,256)   : compute all cell masks (64 cells each), then loss (35 units)
//   blocks [256,1024): loss, 39 units (first 4 mask-free + stashed x-sums)
//   blocks [1024,2048): loss, 38 units (same stash trick)
//   unit = 256 consecutive float4s (one per thread). Total units = 77824 = N4/256.
//   last finishing block reduces partials -> mean, resets sync counters.

#define N_ELEMS   79691776
#define N4        (N_ELEMS / 4)
#define N_CELLS   16384
#define NBLK      2048
#define NTHR      256
#define P_BLOCKS  256
#define E_STASH   4

__device__ unsigned g_masks[N_CELLS];
__device__ double   g_partial[NBLK];
__device__ unsigned g_done = 0;   // presence-complete counter (reset each run)
__device__ unsigned g_fin  = 0;   // finished-block ticket    (reset each run)

__device__ __forceinline__ float ex2_(float x) { float r; asm("ex2.approx.f32 %0, %1;" : "=f"(r) : "f"(x)); return r; }
__device__ __forceinline__ float lg2_(float x) { float r; asm("lg2.approx.f32 %0, %1;" : "=f"(r) : "f"(x)); return r; }
__device__ __forceinline__ unsigned ld_acq(const unsigned* p) {
    unsigned v; asm volatile("ld.acquire.gpu.b32 %0, [%1];" : "=r"(v) : "l"(p)); return v;
}

// mask-free part: al += lg2(1+e^{-|x|}), aa += relu(x)
__device__ __forceinline__ void bce_free(float x, float& al, float& aa) {
    al += lg2_(1.0f + ex2_(fabsf(x) * -1.4426950408889634f));
    aa += fmaxf(x, 0.0f);
}
// mask-aware form: al += lg2 term, aa += relu(se ? -x : x)   [= relu(x) - se*x]
__device__ __forceinline__ void bce_mask(float x, unsigned sgn, float& al, float& aa) {
    al += lg2_(1.0f + ex2_(fabsf(x) * -1.4426950408889634f));
    aa += fmaxf(__int_as_float(__float_as_int(x) ^ sgn), 0.0f);
}

// se-bit lookup for float4 index f (all 4 elems share one cell & class)
__device__ __forceinline__ unsigned se_bit(int f) {
    int w  = (f << 2) & 511;
    int h  = (f >> 7) & 511;
    int bc = f >> 16;                 // b*19 + c, < 304
    int b  = bc / 19;
    int c  = bc - b * 19;
    unsigned mask = g_masks[(b << 10) + ((h >> 4) << 5) + (w >> 4)];
    return (mask >> c) & 1u;
}

__global__ void __launch_bounds__(NTHR, 6) k_fused(const float4* __restrict__ p4,
                                                   const int4*   __restrict__ t4,
                                                   float* __restrict__ out) {
    const int bid = blockIdx.x;
    const int tid = threadIdx.x;

    // per-block unit range (units of 256 float4s)
    int start, cnt;
    if (bid < 256)       { start = bid * 35;                cnt = 35; }
    else if (bid < 1024) { start = 8960  + (bid - 256)*39;  cnt = 39; }
    else                 { start = 38912 + (bid - 1024)*38; cnt = 38; }

    float al0 = 0.f, al1 = 0.f, aa0 = 0.f, aa1 = 0.f;
    int kstart = 0;

    if (bid < P_BLOCKS) {
        // ---------------- presence producer ----------------
        int warp = tid >> 5, lane = tid & 31;
        int cell0 = (bid << 6) + (warp << 3);    // 64 cells/block, 8/warp
#pragma unroll 2
        for (int cc = 0; cc < 8; ++cc) {
            int cell = cell0 + cc;               // = b*1024 + ch*32 + cw
            int b = cell >> 10, rest = cell & 1023, ch = rest >> 5, cw = rest & 31;
            unsigned m = 0;
#pragma unroll
            for (int k = 0; k < 4; ++k) {
                int e = lane + (k << 5);
                int i = e >> 3, jj = e & 7;
                int off = (b << 18) + (((ch << 4) + i) << 9) + (cw << 3) + jj;
                int4 q = __ldg(&t4[off]);
                m |= (1u << (q.x & 31)) | (1u << (q.z & 31));
            }
            m = __reduce_or_sync(0xFFFFFFFFu, m);
            if (lane == 0) g_masks[cell] = m;
        }
        __syncthreads();
        __threadfence();
        if (tid == 0) atomicAdd(&g_done, 1u);
        // wait for ALL masks (need other blocks' cells too)
        if (tid == 0) { while (ld_acq(&g_done) < P_BLOCKS) { } }
        __syncthreads();
    } else {
        // ---------------- waiter: mask-free stash phase ----------------
        float sx[E_STASH];
#pragma unroll
        for (int k = 0; k < E_STASH; ++k) {
            int f = (start + k) * NTHR + tid;
            float4 v = __ldcs(p4 + f);
            bce_free(v.x, al0, aa0); bce_free(v.y, al1, aa1);
            bce_free(v.z, al0, aa0); bce_free(v.w, al1, aa1);
            sx[k] = (v.x + v.y) + (v.z + v.w);
        }
        if (tid == 0) { while (ld_acq(&g_done) < P_BLOCKS) { } }
        __syncthreads();
        // retro-apply  -se * sum(x)  for stashed units
#pragma unroll
        for (int k = 0; k < E_STASH; ++k) {
            int f = (start + k) * NTHR + tid;
            float se = (float)se_bit(f);
            aa0 = fmaf(-se, sx[k], aa0);
        }
        kstart = E_STASH;
    }

    // ---------------- main mask-aware streaming loop ----------------
#pragma unroll 2
    for (int k = kstart; k < cnt; ++k) {
        int f = (start + k) * NTHR + tid;
        float4 v = __ldcs(p4 + f);
        unsigned sgn = se_bit(f) << 31;
        bce_mask(v.x, sgn, al0, aa0); bce_mask(v.y, sgn, al1, aa1);
        bce_mask(v.z, sgn, al0, aa0); bce_mask(v.w, sgn, al1, aa1);
    }

    double acc = (double)(al0 + al1) * 0.6931471805599453 + (double)(aa0 + aa1);

    // deterministic block reduction -> g_partial[bid]
    __shared__ double smem[NTHR / 32];
    __shared__ int s_last;
    for (int o = 16; o > 0; o >>= 1) acc += __shfl_down_sync(0xFFFFFFFFu, acc, o);
    if ((tid & 31) == 0) smem[tid >> 5] = acc;
    __syncthreads();
    if (tid < (NTHR / 32)) {
        double a = smem[tid];
        for (int o = (NTHR / 64); o > 0; o >>= 1) a += __shfl_down_sync(0xFFu, a, o);
        if (tid == 0) g_partial[bid] = a;
    }

    // last block performs the final deterministic reduction
    if (tid == 0) {
        __threadfence();
        unsigned old = atomicAdd(&g_fin, 1u);
        s_last = (old == NBLK - 1);
    }
    __syncthreads();
    if (s_last) {
        __threadfence();
        __shared__ double smem2[NTHR / 32];
        double a = 0.0;
        for (int i = tid; i < NBLK; i += NTHR) a += g_partial[i];
        for (int o = 16; o > 0; o >>= 1) a += __shfl_down_sync(0xFFFFFFFFu, a, o);
        if ((tid & 31) == 0) smem2[tid >> 5] = a;
        __syncthreads();
        if (tid < (NTHR / 32)) {
            double v = smem2[tid];
            for (int o = (NTHR / 64); o > 0; o >>= 1) v += __shfl_down_sync(0xFFu, v, o);
            if (tid == 0) {
                out[0] = (float)(v * (1.0 / (double)N_ELEMS));
                g_fin  = 0;            // reset for next run / graph replay
                g_done = 0;
            }
        }
    }
}

extern "C" void kernel_launch(void* const* d_in, const int* in_sizes, int n_in,
                              void* d_out, int out_size) {
    const float4* preds   = (const float4*)d_in[0];
    const int4*   targets = (const int4*)d_in[1];
    float*        out     = (float*)d_out;
    k_fused<<<NBLK, NTHR>>>(preds, targets, out);
}

// round 6
// speedup vs baseline: 1.0171x; 1.0171x over previous
#include <cuda_runtime.h>
#include <cuda_bf16.h>

// preds:   (16, 19, 512, 512) float32  = 79,691,776 elems
// targets: (16, 1024, 1024)   labels in [0,19) (delivered as int32)
// grid 16 -> 32x32 cells/batch, 16x16 px each.
//
// Single fused kernel, uniform 38-iter grid-stride loss mapping for ALL blocks
// (stride = 8 (b,c)-planes -> cell index loop-invariant, bc += 8 per iter).
//   blocks [0,256):  compute all 16384 cell masks first (64 cells each)
//   blocks [256,2048): stash 5 mask-free iters while masks land, retro-fix
//   last finishing block reduces the 2048 partials deterministically.

#define N_ELEMS   79691776
#define N4        (N_ELEMS / 4)
#define NBLK      2048
#define NTHR      256
#define LOSS_STRIDE (NBLK * NTHR)       // 524288 float4s; N4/LOSS_STRIDE = 38
#define LOSS_ITERS  38
#define P_BLOCKS  256
#define E_STASH   5

__device__ unsigned g_masks[16384];
__device__ double   g_partial[NBLK];
__device__ unsigned g_done = 0;
__device__ unsigned g_fin  = 0;

__device__ __forceinline__ float ex2_(float x) { float r; asm("ex2.approx.f32 %0, %1;" : "=f"(r) : "f"(x)); return r; }
__device__ __forceinline__ float lg2_(float x) { float r; asm("lg2.approx.f32 %0, %1;" : "=f"(r) : "f"(x)); return r; }
__device__ __forceinline__ unsigned ld_acq(const unsigned* p) {
    unsigned v; asm volatile("ld.acquire.gpu.b32 %0, [%1];" : "=r"(v) : "l"(p)); return v;
}

// mask-free: al += lg2(1+e^{-|x|}), aa += relu(x)
__device__ __forceinline__ void bce_free(float x, float& al, float& aa) {
    al += lg2_(1.0f + ex2_(fabsf(x) * -1.4426950408889634f));
    aa += fmaxf(x, 0.0f);
}
// masked: aa += relu(se ? -x : x)  [= relu(x) - se*x]
__device__ __forceinline__ void bce_mask(float x, unsigned sgn, float& al, float& aa) {
    al += lg2_(1.0f + ex2_(fabsf(x) * -1.4426950408889634f));
    aa += fmaxf(__int_as_float(__float_as_int(x) ^ sgn), 0.0f);
}

__global__ void __launch_bounds__(NTHR) k_fused(const float4* __restrict__ p4,
                                                const int4*   __restrict__ t4,
                                                float* __restrict__ out) {
    const int bid  = blockIdx.x;
    const int tid  = threadIdx.x;
    const int gtid = bid * NTHR + tid;

    // loop-invariant geometry (stride covers exactly 8 planes)
    int lin    = gtid << 2;
    int w      = lin & 511;
    int h      = (lin >> 9) & 511;
    int cellhw = ((h >> 4) << 5) + (w >> 4);
    int bc0    = gtid >> 16;               // b*19+c at iter 0; +8 per iter

    float al0 = 0.f, al1 = 0.f, aa0 = 0.f, aa1 = 0.f;
    int kstart = 0;

    if (bid < P_BLOCKS) {
        // ---------------- presence producer (64 cells/block) ----------------
        int warp = tid >> 5, lane = tid & 31;
        int cell0 = (bid << 6) + (warp << 3);
#pragma unroll 2
        for (int cc = 0; cc < 8; ++cc) {
            int cell = cell0 + cc;
            int b = cell >> 10, rest = cell & 1023, ch = rest >> 5, cw = rest & 31;
            unsigned m = 0;
#pragma unroll
            for (int k = 0; k < 4; ++k) {
                int e = lane + (k << 5);
                int i = e >> 3, jj = e & 7;
                int off = (b << 18) + (((ch << 4) + i) << 9) + (cw << 3) + jj;
                int4 q = __ldg(&t4[off]);
                m |= (1u << (q.x & 31)) | (1u << (q.z & 31));
            }
            m = __reduce_or_sync(0xFFFFFFFFu, m);
            if (lane == 0) g_masks[cell] = m;
        }
        __syncthreads();
        __threadfence();
        if (tid == 0) {
            atomicAdd(&g_done, 1u);
            while (ld_acq(&g_done) < P_BLOCKS) { }
        }
        __syncthreads();
    } else {
        // ---------------- waiter: mask-free stash ----------------
        float sx[E_STASH];
#pragma unroll
        for (int k = 0; k < E_STASH; ++k) {
            float4 v = __ldcs(p4 + gtid + k * LOSS_STRIDE);
            bce_free(v.x, al0, aa0); bce_free(v.y, al1, aa1);
            bce_free(v.z, al0, aa0); bce_free(v.w, al1, aa1);
            sx[k] = (v.x + v.y) + (v.z + v.w);
        }
        if (tid == 0) { while (ld_acq(&g_done) < P_BLOCKS) { } }
        __syncthreads();
#pragma unroll
        for (int k = 0; k < E_STASH; ++k) {
            int bc = bc0 + (k << 3);
            int b = bc / 19, c = bc - 19 * b;
            float se = (float)((g_masks[(b << 10) + cellhw] >> c) & 1u);
            aa0 = fmaf(-se, sx[k], aa0);
        }
        kstart = E_STASH;
    }

    // ---------------- lean main loop ----------------
    int bcs = bc0 + (kstart << 3);
    int b = bcs / 19, c = bcs - 19 * b;
#pragma unroll 2
    for (int k = kstart; k < LOSS_ITERS; ++k) {
        float4 v = __ldcs(p4 + gtid + k * LOSS_STRIDE);
        unsigned sgn = ((g_masks[(b << 10) + cellhw] >> c) & 1u) << 31;
        bce_mask(v.x, sgn, al0, aa0); bce_mask(v.y, sgn, al1, aa1);
        bce_mask(v.z, sgn, al0, aa0); bce_mask(v.w, sgn, al1, aa1);
        c += 8; if (c >= 19) { c -= 19; ++b; }
    }

    double acc = (double)(al0 + al1) * 0.6931471805599453 + (double)(aa0 + aa1);

    // deterministic block reduction
    __shared__ double smem[NTHR / 32];
    __shared__ int s_last;
    for (int o = 16; o > 0; o >>= 1) acc += __shfl_down_sync(0xFFFFFFFFu, acc, o);
    if ((tid & 31) == 0) smem[tid >> 5] = acc;
    __syncthreads();
    if (tid < (NTHR / 32)) {
        double a = smem[tid];
        for (int o = (NTHR / 64); o > 0; o >>= 1) a += __shfl_down_sync(0xFFu, a, o);
        if (tid == 0) g_partial[bid] = a;
    }

    // last block: final deterministic reduction + counter reset
    if (tid == 0) {
        __threadfence();
        unsigned old = atomicAdd(&g_fin, 1u);
        s_last = (old == NBLK - 1);
    }
    __syncthreads();
    if (s_last) {
        __threadfence();
        __shared__ double smem2[NTHR / 32];
        double a = 0.0;
        for (int i = tid; i < NBLK; i += NTHR) a += g_partial[i];
        for (int o = 16; o > 0; o >>= 1) a += __shfl_down_sync(0xFFFFFFFFu, a, o);
        if ((tid & 31) == 0) smem2[tid >> 5] = a;
        __syncthreads();
        if (tid < (NTHR / 32)) {
            double v = smem2[tid];
            for (int o = (NTHR / 64); o > 0; o >>= 1) v += __shfl_down_sync(0xFFu, v, o);
            if (tid == 0) {
                out[0] = (float)(v * (1.0 / (double)N_ELEMS));
                g_fin  = 0;
                g_done = 0;
            }
        }
    }
}

extern "C" void kernel_launch(void* const* d_in, const int* in_sizes, int n_in,
                              void* d_out, int out_size) {
    const float4* preds   = (const float4*)d_in[0];
    const int4*   targets = (const int4*)d_in[1];
    float*        out     = (float*)d_out;
    k_fused<<<NBLK, NTHR>>>(preds, targets, out);
}

// round 7
// speedup vs baseline: 1.0372x; 1.0198x over previous
#include <cuda_runtime.h>
#include <cuda_bf16.h>

// preds:   (16, 19, 512, 512) float32 = 79,691,776 elems
// targets: (16, 1024, 1024) labels in [0,19) (delivered as int32)
// grid 16 -> 32x32 cells/batch, 16x16 px each.
//
// Single fused kernel. Uniform 38-iter grid-stride mapping (stride = 8 planes
// -> cell index loop-invariant; bc = bc0 + 8k). Per-thread se-bits for all 38
// iters are precomputed into ONE uint64 after masks are ready, so the hot
// loop has no mask loads and no index arithmetic beyond an immediate shift.

#define N_ELEMS   79691776
#define N4        (N_ELEMS / 4)
#define NBLK      2048
#define NTHR      256
#define LOSS_STRIDE (NBLK * NTHR)       // 524288 float4s; N4/LOSS_STRIDE = 38
#define LOSS_ITERS  38
#define P_BLOCKS  256
#define E_STASH   6

__device__ unsigned g_masks[16384];
__device__ double   g_partial[NBLK];
__device__ unsigned g_done = 0;
__device__ unsigned g_fin  = 0;

__device__ __forceinline__ float ex2_(float x) { float r; asm("ex2.approx.f32 %0, %1;" : "=f"(r) : "f"(x)); return r; }
__device__ __forceinline__ float lg2_(float x) { float r; asm("lg2.approx.f32 %0, %1;" : "=f"(r) : "f"(x)); return r; }
__device__ __forceinline__ unsigned ld_acq(const unsigned* p) {
    unsigned v; asm volatile("ld.acquire.gpu.b32 %0, [%1];" : "=r"(v) : "l"(p)); return v;
}

// mask-free: al += lg2(1+e^{-|x|}), aa += relu(x)
__device__ __forceinline__ void bce_free(float x, float& al, float& aa) {
    al += lg2_(1.0f + ex2_(fabsf(x) * -1.4426950408889634f));
    aa += fmaxf(x, 0.0f);
}
// masked: aa += relu(se ? -x : x)  [= relu(x) - se*x]
__device__ __forceinline__ void bce_mask(float x, unsigned sgn, float& al, float& aa) {
    al += lg2_(1.0f + ex2_(fabsf(x) * -1.4426950408889634f));
    aa += fmaxf(__int_as_float(__float_as_int(x) ^ sgn), 0.0f);
}

__global__ void __launch_bounds__(NTHR) k_fused(const float4* __restrict__ p4,
                                                const int4*   __restrict__ t4,
                                                float* __restrict__ out) {
    const int bid  = blockIdx.x;
    const int tid  = threadIdx.x;
    const int gtid = bid * NTHR + tid;

    // loop-invariant geometry (stride covers exactly 8 (b,c)-planes)
    int lin    = gtid << 2;
    int w      = lin & 511;
    int h      = (lin >> 9) & 511;
    int cellhw = ((h >> 4) << 5) + (w >> 4);
    int c0     = gtid >> 16;               // bc0 < 8 => b starts at 0, c = bc0

    float al0 = 0.f, al1 = 0.f, aa0 = 0.f, aa1 = 0.f;
    float sx[E_STASH];
    int kstart = 0;

    if (bid < P_BLOCKS) {
        // ---------------- presence producer (64 cells/block) ----------------
        int warp = tid >> 5, lane = tid & 31;
        int cell0 = (bid << 6) + (warp << 3);
#pragma unroll 2
        for (int cc = 0; cc < 8; ++cc) {
            int cell = cell0 + cc;
            int b = cell >> 10, rest = cell & 1023, ch = rest >> 5, cw = rest & 31;
            unsigned m = 0;
#pragma unroll
            for (int k = 0; k < 4; ++k) {
                int e = lane + (k << 5);
                int i = e >> 3, jj = e & 7;
                int off = (b << 18) + (((ch << 4) + i) << 9) + (cw << 3) + jj;
                int4 q = __ldg(&t4[off]);
                m |= (1u << (q.x & 31)) | (1u << (q.z & 31));
            }
            m = __reduce_or_sync(0xFFFFFFFFu, m);
            if (lane == 0) g_masks[cell] = m;
        }
        __syncthreads();
        __threadfence();
        if (tid == 0) {
            atomicAdd(&g_done, 1u);
            while (ld_acq(&g_done) < P_BLOCKS) { }
        }
        __syncthreads();
    } else {
        // ---------------- waiter: mask-free stash ----------------
#pragma unroll
        for (int k = 0; k < E_STASH; ++k) {
            float4 v = __ldcs(p4 + gtid + k * LOSS_STRIDE);
            bce_free(v.x, al0, aa0); bce_free(v.y, al1, aa1);
            bce_free(v.z, al0, aa0); bce_free(v.w, al1, aa1);
            sx[k] = (v.x + v.y) + (v.z + v.w);
        }
        if (tid == 0) { while (ld_acq(&g_done) < P_BLOCKS) { } }
        __syncthreads();
        kstart = E_STASH;
    }

    // ---------------- per-thread se-bit precompute (runs once) ----------------
    unsigned long long bits = 0;
    {
        int b = 0, c = c0;
#pragma unroll
        for (int k = 0; k < LOSS_ITERS; ++k) {
            unsigned se = (g_masks[(b << 10) + cellhw] >> c) & 1u;
            bits |= (unsigned long long)se << k;
            c += 8; if (c >= 19) { c -= 19; ++b; }
        }
    }

    // retro-fix stashed iters:  aa -= se_k * sum_x_k
    if (kstart) {
#pragma unroll
        for (int k = 0; k < E_STASH; ++k) {
            float se = (float)((unsigned)(bits >> k) & 1u);
            aa0 = fmaf(-se, sx[k], aa0);
        }
    }

    // ---------------- lean main loop: no mask loads, no wrap chain ----------------
#pragma unroll 2
    for (int k = kstart; k < LOSS_ITERS; ++k) {
        float4 v = __ldcs(p4 + gtid + k * LOSS_STRIDE);
        unsigned sgn = ((unsigned)(bits >> k) & 1u) << 31;
        bce_mask(v.x, sgn, al0, aa0); bce_mask(v.y, sgn, al1, aa1);
        bce_mask(v.z, sgn, al0, aa0); bce_mask(v.w, sgn, al1, aa1);
    }

    double acc = (double)(al0 + al1) * 0.6931471805599453 + (double)(aa0 + aa1);

    // deterministic block reduction
    __shared__ double smem[NTHR / 32];
    __shared__ int s_last;
    for (int o = 16; o > 0; o >>= 1) acc += __shfl_down_sync(0xFFFFFFFFu, acc, o);
    if ((tid & 31) == 0) smem[tid >> 5] = acc;
    __syncthreads();
    if (tid < (NTHR / 32)) {
        double a = smem[tid];
        for (int o = (NTHR / 64); o > 0; o >>= 1) a += __shfl_down_sync(0xFFu, a, o);
        if (tid == 0) g_partial[bid] = a;
    }

    // last block: final deterministic reduction + counter reset
    if (tid == 0) {
        __threadfence();
        unsigned old = atomicAdd(&g_fin, 1u);
        s_last = (old == NBLK - 1);
    }
    __syncthreads();
    if (s_last) {
        __threadfence();
        __shared__ double smem2[NTHR / 32];
        double a = 0.0;
        for (int i = tid; i < NBLK; i += NTHR) a += g_partial[i];
        for (int o = 16; o > 0; o >>= 1) a += __shfl_down_sync(0xFFFFFFFFu, a, o);
        if ((tid & 31) == 0) smem2[tid >> 5] = a;
        __syncthreads();
        if (tid < (NTHR / 32)) {
            double v = smem2[tid];
            for (int o = (NTHR / 64); o > 0; o >>= 1) v += __shfl_down_sync(0xFFu, v, o);
            if (tid == 0) {
                out[0] = (float)(v * (1.0 / (double)N_ELEMS));
                g_fin  = 0;
                g_done = 0;
            }
        }
    }
}

extern "C" void kernel_launch(void* const* d_in, const int* in_sizes, int n_in,
                              void* d_out, int out_size) {
    const float4* preds   = (const float4*)d_in[0];
    const int4*   targets = (const int4*)d_in[1];
    float*        out     = (float*)d_out;
    k_fused<<<NBLK, NTHR>>>(preds, targets, out);
}

// round 8
// speedup vs baseline: 1.1006x; 1.0610x over previous
#include <cuda_runtime.h>
#include <cuda_bf16.h>

// preds:   (16, 19, 512, 512) float32 = 79,691,776 elems
// targets: (16, 1024, 1024) labels in [0,19) (delivered as int32)
// grid 16 -> 32x32 cells/batch, 16x16 px each.
//
// Two kernels (fusion of presence into the stream kernel measurably caps
// DRAM at ~61% vs 76% standalone -> keep the split):
//   k_presence: one warp per 2 cells, 8 independent int4 loads/thread (MLP=8)
//   k_loss:     38-iter grid-stride; per-thread se-bits precomputed into one
//               uint64; final reduction fused via last-block ticket.

#define N_ELEMS   79691776
#define N4        (N_ELEMS / 4)
#define NBLK      2048
#define NTHR      256
#define LOSS_STRIDE (NBLK * NTHR)       // 524288 float4s; N4/LOSS_STRIDE = 38
#define LOSS_ITERS  38

__device__ unsigned g_masks[16384];
__device__ double   g_partial[NBLK];
__device__ unsigned g_fin = 0;

__device__ __forceinline__ float ex2_(float x) { float r; asm("ex2.approx.f32 %0, %1;" : "=f"(r) : "f"(x)); return r; }
__device__ __forceinline__ float lg2_(float x) { float r; asm("lg2.approx.f32 %0, %1;" : "=f"(r) : "f"(x)); return r; }

// ---------------------------------------------------------------------------
// Kernel 1: per-cell class-presence bitmask (stride-2 NN downsample).
// One warp per 2 cells; all 8 int4 loads issued back-to-back (MLP=8/thread).
// ---------------------------------------------------------------------------
__global__ void __launch_bounds__(256) k_presence(const int4* __restrict__ t4) {
    int gwarp = (blockIdx.x * blockDim.x + threadIdx.x) >> 5;  // 0..8191
    int lane  = threadIdx.x & 31;
    int cellA = gwarp << 1;            // cells 2w, 2w+1 (same batch, same cell row)
    int bA    = cellA >> 10;
    int restA = cellA & 1023;
    int chA   = restA >> 5;
    int cwA   = restA & 31;            // even; cellB has cwA+1

    // base int4 offset of cell (b, ch, cw): b*2^18 + ch*16*512 + cw*8
    int baseA = (bA << 18) + (chA << 13) + (cwA << 3);
    int baseB = baseA + 8;

    int4 qa[4], qb[4];
#pragma unroll
    for (int k = 0; k < 4; ++k) {
        int e = lane + (k << 5);       // 0..127: 16 rows x 8 int4/row
        int i = e >> 3, jj = e & 7;
        int roff = (i << 9) + jj;      // row stride 512 int4s (2 orig rows)
        qa[k] = __ldg(&t4[baseA + roff]);
        qb[k] = __ldg(&t4[baseB + roff]);
    }
    unsigned mA = 0, mB = 0;
#pragma unroll
    for (int k = 0; k < 4; ++k) {
        mA |= (1u << (qa[k].x & 31)) | (1u << (qa[k].z & 31));
        mB |= (1u << (qb[k].x & 31)) | (1u << (qb[k].z & 31));
    }
    mA = __reduce_or_sync(0xFFFFFFFFu, mA);
    mB = __reduce_or_sync(0xFFFFFFFFu, mB);
    if (lane == 0) { g_masks[cellA] = mA; g_masks[cellA + 1] = mB; }
}

// bce terms: al += lg2(1+e^{-|x|});  aa += relu(se ? -x : x) [= relu(x)-se*x]
__device__ __forceinline__ void bce_mask(float x, unsigned sgn, float& al, float& aa) {
    al += lg2_(1.0f + ex2_(fabsf(x) * -1.4426950408889634f));
    aa += fmaxf(__int_as_float(__float_as_int(x) ^ sgn), 0.0f);
}

// ---------------------------------------------------------------------------
// Kernel 2: streaming loss + fused final reduction.
// ---------------------------------------------------------------------------
__global__ void __launch_bounds__(NTHR) k_loss(const float4* __restrict__ p4,
                                               float* __restrict__ out) {
    const int tid  = threadIdx.x;
    const int gtid = blockIdx.x * NTHR + tid;

    // loop-invariant geometry (stride covers exactly 8 (b,c)-planes)
    int lin    = gtid << 2;
    int w      = lin & 511;
    int h      = (lin >> 9) & 511;
    int cellhw = ((h >> 4) << 5) + (w >> 4);
    int c0     = gtid >> 16;               // bc0 < 8: b=0, c=c0 at iter 0

    // precompute all 38 se-bits into one uint64 (independent L1/L2-hit loads)
    unsigned long long bits = 0;
    {
        int b = 0, c = c0;
#pragma unroll
        for (int k = 0; k < LOSS_ITERS; ++k) {
            unsigned se = (g_masks[(b << 10) + cellhw] >> c) & 1u;
            bits |= (unsigned long long)se << k;
            c += 8; if (c >= 19) { c -= 19; ++b; }
        }
    }

    // lean main loop: one LDG.128 + math per iter, se via immediate shift
    float al0 = 0.f, al1 = 0.f, aa0 = 0.f, aa1 = 0.f;
#pragma unroll 2
    for (int k = 0; k < LOSS_ITERS; ++k) {
        float4 v = __ldcs(p4 + gtid + k * LOSS_STRIDE);
        unsigned sgn = ((unsigned)(bits >> k) & 1u) << 31;
        bce_mask(v.x, sgn, al0, aa0); bce_mask(v.y, sgn, al1, aa1);
        bce_mask(v.z, sgn, al0, aa0); bce_mask(v.w, sgn, al1, aa1);
    }

    double acc = (double)(al0 + al1) * 0.6931471805599453 + (double)(aa0 + aa1);

    // deterministic block reduction -> g_partial
    __shared__ double smem[NTHR / 32];
    __shared__ int s_last;
    for (int o = 16; o > 0; o >>= 1) acc += __shfl_down_sync(0xFFFFFFFFu, acc, o);
    if ((tid & 31) == 0) smem[tid >> 5] = acc;
    __syncthreads();
    if (tid < (NTHR / 32)) {
        double a = smem[tid];
        for (int o = (NTHR / 64); o > 0; o >>= 1) a += __shfl_down_sync(0xFFu, a, o);
        if (tid == 0) g_partial[blockIdx.x] = a;
    }

    // last block: final deterministic reduction + write + counter reset
    if (tid == 0) {
        __threadfence();
        unsigned old = atomicAdd(&g_fin, 1u);
        s_last = (old == NBLK - 1);
    }
    __syncthreads();
    if (s_last) {
        __threadfence();
        __shared__ double smem2[NTHR / 32];
        double a = 0.0;
        for (int i = tid; i < NBLK; i += NTHR) a += g_partial[i];
        for (int o = 16; o > 0; o >>= 1) a += __shfl_down_sync(0xFFFFFFFFu, a, o);
        if ((tid & 31) == 0) smem2[tid >> 5] = a;
        __syncthreads();
        if (tid < (NTHR / 32)) {
            double v = smem2[tid];
            for (int o = (NTHR / 64); o > 0; o >>= 1) v += __shfl_down_sync(0xFFu, v, o);
            if (tid == 0) {
                out[0] = (float)(v * (1.0 / (double)N_ELEMS));
                g_fin = 0;   // reset for next run / graph replay
            }
        }
    }
}

extern "C" void kernel_launch(void* const* d_in, const int* in_sizes, int n_in,
                              void* d_out, int out_size) {
    const float4* preds   = (const float4*)d_in[0];
    const int4*   targets = (const int4*)d_in[1];
    float*        out     = (float*)d_out;
    k_presence<<<1024, 256>>>(targets);
    k_loss<<<NBLK, NTHR>>>(preds, out);
}